// round 1
// baseline (speedup 1.0000x reference)
#include <cuda_runtime.h>
#include <math.h>

#define BATCH   4
#define NSEQ    4096
#define DIM     512
#define MTOT    (BATCH*NSEQ)   // 16384

// Scratch (allocation-free rule: device globals)
__device__ float g_Q[(size_t)MTOT * DIM];
__device__ float g_K[(size_t)MTOT * DIM];
__device__ float g_V[(size_t)MTOT * DIM];
__device__ float g_S[(size_t)BATCH * NSEQ * NSEQ];

// ---------------------------------------------------------------------------
// C = alpha * A @ op(B)
//   A: row-major M x K
//   TRANS_B=true : B row-major N x K  (C += A * B^T)  -- both K-contiguous
//   TRANS_B=false: B row-major K x N  (C += A * B)
// 128x128 tile, BK=8, 256 threads, 8x8 per thread. All dims multiples of tile.
// ---------------------------------------------------------------------------
template<bool TRANS_B>
__global__ __launch_bounds__(256, 2)
void gemm128(const float* __restrict__ A, const float* __restrict__ B,
             float* __restrict__ C, int M, int N, int K,
             size_t sA, size_t sB, size_t sC, float alpha)
{
    A += (size_t)blockIdx.z * sA;
    B += (size_t)blockIdx.z * sB;
    C += (size_t)blockIdx.z * sC;

    __shared__ float As[8][128];
    __shared__ float Bs[8][128];

    const int tid = threadIdx.x;
    const int tx  = tid & 15;       // 0..15  -> col group
    const int ty  = tid >> 4;       // 0..15  -> row group
    const int bm  = blockIdx.y * 128;
    const int bn  = blockIdx.x * 128;

    float c[8][8] = {};

    // A tile load: 128 rows x 8 k, one float4 per thread
    const int a_row = tid >> 1;         // 0..127
    const int a_col = (tid & 1) * 4;    // 0 or 4
    const float* Aptr = A + (size_t)(bm + a_row) * K + a_col;

    // B tile load
    const float* Bptr;
    int b_row, b_col;
    if (TRANS_B) {
        b_row = tid >> 1;               // n within tile
        b_col = (tid & 1) * 4;          // k within tile
        Bptr = B + (size_t)(bn + b_row) * K + b_col;
    } else {
        b_row = tid >> 5;               // k within tile: 0..7
        b_col = (tid & 31) * 4;         // n within tile: 0..124
        Bptr = B + (size_t)b_row * N + bn + b_col;
    }

    for (int k0 = 0; k0 < K; k0 += 8) {
        float4 av = *(const float4*)Aptr;  Aptr += 8;
        As[a_col + 0][a_row] = av.x;
        As[a_col + 1][a_row] = av.y;
        As[a_col + 2][a_row] = av.z;
        As[a_col + 3][a_row] = av.w;

        if (TRANS_B) {
            float4 bv = *(const float4*)Bptr;  Bptr += 8;
            Bs[b_col + 0][b_row] = bv.x;
            Bs[b_col + 1][b_row] = bv.y;
            Bs[b_col + 2][b_row] = bv.z;
            Bs[b_col + 3][b_row] = bv.w;
        } else {
            float4 bv = *(const float4*)Bptr;  Bptr += (size_t)8 * N;
            *(float4*)&Bs[b_row][b_col] = bv;
        }
        __syncthreads();

        #pragma unroll
        for (int kk = 0; kk < 8; kk++) {
            float a[8], b[8];
            *(float4*)(a)     = *(const float4*)&As[kk][ty * 8];
            *(float4*)(a + 4) = *(const float4*)&As[kk][ty * 8 + 4];
            *(float4*)(b)     = *(const float4*)&Bs[kk][tx * 8];
            *(float4*)(b + 4) = *(const float4*)&Bs[kk][tx * 8 + 4];
            #pragma unroll
            for (int i = 0; i < 8; i++)
                #pragma unroll
                for (int j = 0; j < 8; j++)
                    c[i][j] += a[i] * b[j];
        }
        __syncthreads();
    }

    #pragma unroll
    for (int i = 0; i < 8; i++) {
        size_t off = (size_t)(bm + ty * 8 + i) * N + bn + tx * 8;
        float4 v0 = make_float4(c[i][0] * alpha, c[i][1] * alpha,
                                c[i][2] * alpha, c[i][3] * alpha);
        float4 v1 = make_float4(c[i][4] * alpha, c[i][5] * alpha,
                                c[i][6] * alpha, c[i][7] * alpha);
        *(float4*)&C[off]     = v0;
        *(float4*)&C[off + 4] = v1;
    }
}

// ---------------------------------------------------------------------------
// Row softmax for 4096-wide rows. One CTA (256 threads) per row; the full row
// lives in registers (16 floats/thread) -> one read + one write of g_S.
// ---------------------------------------------------------------------------
__global__ __launch_bounds__(256)
void softmax4096(float* __restrict__ S)
{
    const size_t row = blockIdx.x;
    float* p = S + row * (size_t)NSEQ;
    const int tid  = threadIdx.x;
    const int lane = tid & 31;
    const int warp = tid >> 5;

    __shared__ float red[8];

    float v[16];
    float m = -3.4e38f;
    #pragma unroll
    for (int i = 0; i < 16; i++) {
        v[i] = p[tid + i * 256];
        m = fmaxf(m, v[i]);
    }
    // block max
    #pragma unroll
    for (int o = 16; o > 0; o >>= 1) m = fmaxf(m, __shfl_xor_sync(0xffffffffu, m, o));
    if (lane == 0) red[warp] = m;
    __syncthreads();
    if (tid < 8) {
        float t = red[tid];
        #pragma unroll
        for (int o = 4; o > 0; o >>= 1) t = fmaxf(t, __shfl_xor_sync(0xffu, t, o));
        if (tid == 0) red[0] = t;
    }
    __syncthreads();
    m = red[0];
    __syncthreads();

    float s = 0.f;
    #pragma unroll
    for (int i = 0; i < 16; i++) {
        v[i] = expf(v[i] - m);
        s += v[i];
    }
    // block sum
    #pragma unroll
    for (int o = 16; o > 0; o >>= 1) s += __shfl_xor_sync(0xffffffffu, s, o);
    if (lane == 0) red[warp] = s;
    __syncthreads();
    if (tid < 8) {
        float t = red[tid];
        #pragma unroll
        for (int o = 4; o > 0; o >>= 1) t += __shfl_xor_sync(0xffu, t, o);
        if (tid == 0) red[0] = t;
    }
    __syncthreads();
    const float inv = 1.0f / red[0];

    #pragma unroll
    for (int i = 0; i < 16; i++)
        p[tid + i * 256] = v[i] * inv;
}

// ---------------------------------------------------------------------------
extern "C" void kernel_launch(void* const* d_in, const int* in_sizes, int n_in,
                              void* d_out, int out_size)
{
    const float* x  = (const float*)d_in[0];
    const float* wq = (const float*)d_in[1];
    const float* wk = (const float*)d_in[2];
    const float* wv = (const float*)d_in[3];
    float* out = (float*)d_out;

    float *Q, *K, *V, *S;
    cudaGetSymbolAddress((void**)&Q, g_Q);
    cudaGetSymbolAddress((void**)&K, g_K);
    cudaGetSymbolAddress((void**)&V, g_V);
    cudaGetSymbolAddress((void**)&S, g_S);

    const dim3 blk(256);
    const float inv_sqrt_d = 0.04419417382415922f;  // 1/sqrt(512)

    // QKV projections: [16384,512] @ [512,512]^T (NT)
    gemm128<true><<<dim3(DIM / 128, MTOT / 128, 1), blk>>>(
        x, wq, Q, MTOT, DIM, DIM, 0, 0, 0, 1.0f);
    gemm128<true><<<dim3(DIM / 128, MTOT / 128, 1), blk>>>(
        x, wk, K, MTOT, DIM, DIM, 0, 0, 0, 1.0f);
    gemm128<true><<<dim3(DIM / 128, MTOT / 128, 1), blk>>>(
        x, wv, V, MTOT, DIM, DIM, 0, 0, 0, 1.0f);

    // S = (Q @ K^T) / sqrt(512), per batch (NT)
    gemm128<true><<<dim3(NSEQ / 128, NSEQ / 128, BATCH), blk>>>(
        Q, K, S, NSEQ, NSEQ, DIM,
        (size_t)NSEQ * DIM, (size_t)NSEQ * DIM, (size_t)NSEQ * NSEQ, inv_sqrt_d);

    // row softmax (mask is all-False in the reference -> full attention)
    softmax4096<<<BATCH * NSEQ, blk>>>(S);

    // O = P @ V, per batch (NN)
    gemm128<false><<<dim3(DIM / 128, NSEQ / 128, BATCH), blk>>>(
        S, V, out, NSEQ, DIM, NSEQ,
        (size_t)NSEQ * NSEQ, (size_t)NSEQ * DIM, (size_t)NSEQ * DIM, 1.0f);
}

// round 4
// speedup vs baseline: 2.7166x; 2.7166x over previous
#include <cuda_runtime.h>
#include <cuda_bf16.h>
#include <cstdint>
#include <math.h>

#define BATCH   4
#define NSEQ    4096
#define DIM     512
#define MTOT    (BATCH*NSEQ)   // 16384

// ---------------- scratch (allocation-free rule: device globals) ----------------
__device__ __align__(256) __nv_bfloat16 g_xh[(size_t)MTOT*DIM];
__device__ __align__(256) __nv_bfloat16 g_xl[(size_t)MTOT*DIM];
__device__ __align__(256) __nv_bfloat16 g_wh[3*DIM*DIM];
__device__ __align__(256) __nv_bfloat16 g_wl[3*DIM*DIM];
__device__ __align__(256) __nv_bfloat16 g_Qh[(size_t)MTOT*DIM];
__device__ __align__(256) __nv_bfloat16 g_Ql[(size_t)MTOT*DIM];
__device__ __align__(256) __nv_bfloat16 g_Kh[(size_t)MTOT*DIM];
__device__ __align__(256) __nv_bfloat16 g_Kl[(size_t)MTOT*DIM];
__device__ __align__(256) __nv_bfloat16 g_Vth[(size_t)BATCH*DIM*NSEQ];
__device__ __align__(256) __nv_bfloat16 g_Vtl[(size_t)BATCH*DIM*NSEQ];
__device__ __align__(256) float          g_S [(size_t)BATCH*NSEQ*NSEQ];
__device__ __align__(256) __nv_bfloat16 g_Ph[(size_t)BATCH*NSEQ*NSEQ];
__device__ __align__(256) __nv_bfloat16 g_Pl[(size_t)BATCH*NSEQ*NSEQ];

// ---------------- helpers (plain sm_80-level PTX: valid on sm_103 target) -------
__device__ __forceinline__ uint32_t smem_to_u32(const void* p) {
    uint32_t a;
    asm("{ .reg .u64 t; cvta.to.shared.u64 t, %1; cvt.u32.u64 %0, t; }" : "=r"(a) : "l"(p));
    return a;
}
__device__ __forceinline__ void cp16(uint32_t dst, const void* src) {
    asm volatile("cp.async.cg.shared.global [%0], [%1], 16;" :: "r"(dst), "l"(src));
}
#define CP_COMMIT() asm volatile("cp.async.commit_group;")
#define CP_WAIT1()  asm volatile("cp.async.wait_group 1;")

#define LDSM_X4(r0,r1,r2,r3, addr) \
    asm volatile("ldmatrix.sync.aligned.m8n8.x4.shared.b16 {%0,%1,%2,%3}, [%4];" \
        : "=r"(r0), "=r"(r1), "=r"(r2), "=r"(r3) : "r"(addr))

#define MMA16816(d, a, b0, b1) \
    asm volatile("mma.sync.aligned.m16n8k16.row.col.f32.bf16.bf16.f32 " \
        "{%0,%1,%2,%3}, {%4,%5,%6,%7}, {%8,%9}, {%0,%1,%2,%3};" \
        : "+f"((d)[0]), "+f"((d)[1]), "+f"((d)[2]), "+f"((d)[3]) \
        : "r"((a)[0]), "r"((a)[1]), "r"((a)[2]), "r"((a)[3]), "r"(b0), "r"(b1))

// 16B-chunk XOR swizzle for a [rows][32 bf16] tile (64B rows):
// chunk' = c ^ ((r>>1)&3)  -> ldmatrix 8-row wavefronts hit 8 distinct 16B slots / 128B.
__device__ __forceinline__ uint32_t swz(int r, int c) {
    return (uint32_t)(r * 64 + ((c ^ ((r >> 1) & 3)) << 4));
}

// ---------------------------------------------------------------------------
// bf16 hi/lo compensated GEMM on legacy tensor cores (mma.sync m16n8k16).
// C[M,N] = scale * (A @ B^T), A,B K-major.  Logical K' = 3K via operand phases
//   {(Ah,Bh), (Al,Bh), (Ah,Bl)}  (Al*Bl term ~2^-16, dropped).
// 128x128 CTA tile, BK=32, 3-stage cp.async pipeline, 8 warps (2m x 4n, 64x32).
// EPI: 0 = fp32 out * scale; 1 = bf16 hi/lo out; 2 = bf16 hi/lo transposed (V^T).
// ---------------------------------------------------------------------------
#define STAGES      3
#define STAGE_BYTES 16384   // A 8KB + B 8KB

template<int EPI>
__global__ __launch_bounds__(256)
void mma_gemm(const __nv_bfloat16* __restrict__ Ah, const __nv_bfloat16* __restrict__ Al,
              const __nv_bfloat16* __restrict__ Bh, const __nv_bfloat16* __restrict__ Bl,
              int K, size_t sA, size_t sB, float scale,
              float* __restrict__ Cf,
              __nv_bfloat16* __restrict__ Ch, __nv_bfloat16* __restrict__ Cl,
              size_t sC, int ldC)
{
    __shared__ __align__(1024) char smem[STAGES * STAGE_BYTES];
    const uint32_t sm0 = smem_to_u32(smem);
    const int tid  = threadIdx.x;
    const int wid  = tid >> 5;
    const int lane = tid & 31;
    const int wm   = wid & 1;        // 0..1  (64-row half)
    const int wn   = wid >> 1;       // 0..3  (32-col quarter)
    const int bm   = blockIdx.y * 128;
    const int bn   = blockIdx.x * 128;
    const int z    = blockIdx.z;

    const __nv_bfloat16* A0 = Ah + (size_t)z * sA + (size_t)bm * K;
    const __nv_bfloat16* A1 = Al + (size_t)z * sA + (size_t)bm * K;
    const __nv_bfloat16* B0 = Bh + (size_t)z * sB + (size_t)bn * K;
    const __nv_bfloat16* B1 = Bl + (size_t)z * sB + (size_t)bn * K;
    const __nv_bfloat16* PA[3] = {A0, A1, A0};
    const __nv_bfloat16* PB[3] = {B0, B0, B1};

    const int PER = K >> 5;     // 32-wide chunks per phase
    const int NCH = 3 * PER;

    float acc[4][4][4];
    #pragma unroll
    for (int i = 0; i < 4; i++)
        #pragma unroll
        for (int j = 0; j < 4; j++)
            #pragma unroll
            for (int e = 0; e < 4; e++) acc[i][j][e] = 0.f;

    // stage load: 128 rows x 4 chunks of 16B for A and for B; 4 cp.async/thread
    auto issue = [&](int i, int s) {
        int p  = (i >= PER) + (i >= 2 * PER);
        int kc = (i - p * PER) << 5;
        const __nv_bfloat16* Ap = PA[p] + kc;
        const __nv_bfloat16* Bp = PB[p] + kc;
        uint32_t sa = sm0 + (uint32_t)s * STAGE_BYTES;
        #pragma unroll
        for (int u = 0; u < 2; u++) {
            int id = tid + u * 256;
            int r  = id >> 2;
            int c  = id & 3;
            uint32_t sw = swz(r, c);
            cp16(sa + sw,        Ap + (size_t)r * K + c * 8);
            cp16(sa + 8192 + sw, Bp + (size_t)r * K + c * 8);
        }
        CP_COMMIT();
    };

    issue(0, 0);
    issue(1, 1);

    int cs = 0;
    for (int i = 0; i < NCH; i++) {
        CP_WAIT1();
        __syncthreads();
        if (i + 2 < NCH) issue(i + 2, (cs + 2) % STAGES);

        uint32_t sa = sm0 + (uint32_t)cs * STAGE_BYTES;
        #pragma unroll
        for (int ks = 0; ks < 2; ks++) {
            uint32_t af[4][4], bfr[2][4];
            #pragma unroll
            for (int mi = 0; mi < 4; mi++) {
                int r = wm * 64 + mi * 16 + (lane & 15);
                int c = 2 * ks + (lane >> 4);
                LDSM_X4(af[mi][0], af[mi][1], af[mi][2], af[mi][3], sa + swz(r, c));
            }
            #pragma unroll
            for (int g = 0; g < 2; g++) {
                int n = wn * 32 + g * 16 + (lane & 7) + ((lane >> 4) & 1) * 8;
                int c = 2 * ks + ((lane >> 3) & 1);
                LDSM_X4(bfr[g][0], bfr[g][1], bfr[g][2], bfr[g][3],
                        sa + 8192 + swz(n, c));
            }
            #pragma unroll
            for (int mi = 0; mi < 4; mi++)
                #pragma unroll
                for (int ni = 0; ni < 4; ni++)
                    MMA16816(acc[mi][ni], af[mi],
                             bfr[ni >> 1][(ni & 1) * 2], bfr[ni >> 1][(ni & 1) * 2 + 1]);
        }
        cs = (cs + 1) % STAGES;
    }

    // ------------------------- epilogue -------------------------
    #pragma unroll
    for (int mi = 0; mi < 4; mi++) {
        int row0 = bm + wm * 64 + mi * 16 + (lane >> 2);
        #pragma unroll
        for (int ni = 0; ni < 4; ni++) {
            int col = bn + wn * 32 + ni * 8 + (lane & 3) * 2;
            float v0 = acc[mi][ni][0] * scale, v1 = acc[mi][ni][1] * scale;
            float v2 = acc[mi][ni][2] * scale, v3 = acc[mi][ni][3] * scale;
            if (EPI == 0) {
                float* base = Cf + (size_t)z * sC;
                *(float2*)(base + (size_t)row0       * ldC + col) = make_float2(v0, v1);
                *(float2*)(base + (size_t)(row0 + 8) * ldC + col) = make_float2(v2, v3);
            } else if (EPI == 1) {
                __nv_bfloat16 h0 = __float2bfloat16(v0), h1 = __float2bfloat16(v1);
                __nv_bfloat16 h2 = __float2bfloat16(v2), h3 = __float2bfloat16(v3);
                __nv_bfloat162 hp0; hp0.x = h0; hp0.y = h1;
                __nv_bfloat162 hp1; hp1.x = h2; hp1.y = h3;
                __nv_bfloat162 lp0, lp1;
                lp0.x = __float2bfloat16(v0 - __bfloat162float(h0));
                lp0.y = __float2bfloat16(v1 - __bfloat162float(h1));
                lp1.x = __float2bfloat16(v2 - __bfloat162float(h2));
                lp1.y = __float2bfloat16(v3 - __bfloat162float(h3));
                *(__nv_bfloat162*)(Ch + (size_t)row0       * ldC + col) = hp0;
                *(__nv_bfloat162*)(Cl + (size_t)row0       * ldC + col) = lp0;
                *(__nv_bfloat162*)(Ch + (size_t)(row0 + 8) * ldC + col) = hp1;
                *(__nv_bfloat162*)(Cl + (size_t)(row0 + 8) * ldC + col) = lp1;
            } else {   // EPI == 2: transposed hi/lo (V^T[b][dim][seq])
                float vv[4] = {v0, v1, v2, v3};
                #pragma unroll
                for (int e = 0; e < 4; e++) {
                    int m  = row0 + (e >> 1) * 8;
                    int cc = col + (e & 1);
                    int b  = m >> 12;
                    int sq = m & (NSEQ - 1);
                    __nv_bfloat16 h = __float2bfloat16(vv[e]);
                    size_t off = (size_t)b * sC + (size_t)cc * ldC + sq;
                    Ch[off] = h;
                    Cl[off] = __float2bfloat16(vv[e] - __bfloat162float(h));
                }
            }
        }
    }
}

// ---------------------------------------------------------------------------
// fp32 -> bf16 hi/lo split
// ---------------------------------------------------------------------------
__global__ __launch_bounds__(256)
void split_fp32(const float* __restrict__ in, __nv_bfloat16* __restrict__ h,
                __nv_bfloat16* __restrict__ l, int n)
{
    int i = blockIdx.x * 256 + threadIdx.x;
    if (i < n) {
        float v = in[i];
        __nv_bfloat16 hh = __float2bfloat16(v);
        h[i] = hh;
        l[i] = __float2bfloat16(v - __bfloat162float(hh));
    }
}

// ---------------------------------------------------------------------------
// Row softmax (4096 wide) + bf16 hi/lo split of P. One CTA (256 thr) per row.
// ---------------------------------------------------------------------------
__global__ __launch_bounds__(256)
void softmax_split(const float* __restrict__ S, __nv_bfloat16* __restrict__ Ph,
                   __nv_bfloat16* __restrict__ Pl)
{
    const size_t row = blockIdx.x;
    const float* p = S + row * (size_t)NSEQ;
    const int tid  = threadIdx.x;
    const int lane = tid & 31;
    const int warp = tid >> 5;

    __shared__ float red[8];

    float v[16];
    float m = -3.4e38f;
    #pragma unroll
    for (int i = 0; i < 16; i++) {
        v[i] = p[tid + i * 256];
        m = fmaxf(m, v[i]);
    }
    #pragma unroll
    for (int o = 16; o > 0; o >>= 1) m = fmaxf(m, __shfl_xor_sync(0xffffffffu, m, o));
    if (lane == 0) red[warp] = m;
    __syncthreads();
    if (tid < 8) {
        float t = red[tid];
        #pragma unroll
        for (int o = 4; o > 0; o >>= 1) t = fmaxf(t, __shfl_xor_sync(0xffu, t, o));
        if (tid == 0) red[0] = t;
    }
    __syncthreads();
    m = red[0];
    __syncthreads();

    float s = 0.f;
    #pragma unroll
    for (int i = 0; i < 16; i++) {
        v[i] = expf(v[i] - m);
        s += v[i];
    }
    #pragma unroll
    for (int o = 16; o > 0; o >>= 1) s += __shfl_xor_sync(0xffffffffu, s, o);
    if (lane == 0) red[warp] = s;
    __syncthreads();
    if (tid < 8) {
        float t = red[tid];
        #pragma unroll
        for (int o = 4; o > 0; o >>= 1) t += __shfl_xor_sync(0xffu, t, o);
        if (tid == 0) red[0] = t;
    }
    __syncthreads();
    const float inv = 1.0f / red[0];

    #pragma unroll
    for (int i = 0; i < 16; i++) {
        float pv = v[i] * inv;
        __nv_bfloat16 h = __float2bfloat16(pv);
        size_t idx = row * (size_t)NSEQ + tid + i * 256;
        Ph[idx] = h;
        Pl[idx] = __float2bfloat16(pv - __bfloat162float(h));
    }
}

// ---------------------------------------------------------------------------
extern "C" void kernel_launch(void* const* d_in, const int* in_sizes, int n_in,
                              void* d_out, int out_size)
{
    const float* x  = (const float*)d_in[0];
    const float* wq = (const float*)d_in[1];
    const float* wk = (const float*)d_in[2];
    const float* wv = (const float*)d_in[3];
    float* out = (float*)d_out;

    __nv_bfloat16 *xh, *xl, *wh, *wl, *Qh, *Ql, *Kh, *Kl, *Vth, *Vtl, *Ph, *Pl;
    float *S;
    cudaGetSymbolAddress((void**)&xh, g_xh);   cudaGetSymbolAddress((void**)&xl, g_xl);
    cudaGetSymbolAddress((void**)&wh, g_wh);   cudaGetSymbolAddress((void**)&wl, g_wl);
    cudaGetSymbolAddress((void**)&Qh, g_Qh);   cudaGetSymbolAddress((void**)&Ql, g_Ql);
    cudaGetSymbolAddress((void**)&Kh, g_Kh);   cudaGetSymbolAddress((void**)&Kl, g_Kl);
    cudaGetSymbolAddress((void**)&Vth, g_Vth); cudaGetSymbolAddress((void**)&Vtl, g_Vtl);
    cudaGetSymbolAddress((void**)&S, g_S);
    cudaGetSymbolAddress((void**)&Ph, g_Ph);   cudaGetSymbolAddress((void**)&Pl, g_Pl);

    const int NX = MTOT * DIM;      // 8388608
    const int NW = DIM * DIM;       // 262144
    split_fp32<<<(NX + 255) / 256, 256>>>(x, xh, xl, NX);
    split_fp32<<<(NW + 255) / 256, 256>>>(wq, wh + 0*NW, wl + 0*NW, NW);
    split_fp32<<<(NW + 255) / 256, 256>>>(wk, wh + 1*NW, wl + 1*NW, NW);
    split_fp32<<<(NW + 255) / 256, 256>>>(wv, wh + 2*NW, wl + 2*NW, NW);

    const float inv_sqrt_d = 0.04419417382415922f;  // 1/sqrt(512)
    const dim3 blk(256);

    // Projections (M=16384, N=512, K=512); Q pre-scaled by 1/sqrt(d)
    mma_gemm<1><<<dim3(4, 128, 1), blk>>>(
        xh, xl, wh + 0*NW, wl + 0*NW, DIM, 0, 0, inv_sqrt_d,
        nullptr, Qh, Ql, 0, DIM);
    mma_gemm<1><<<dim3(4, 128, 1), blk>>>(
        xh, xl, wh + 1*NW, wl + 1*NW, DIM, 0, 0, 1.0f,
        nullptr, Kh, Kl, 0, DIM);
    mma_gemm<2><<<dim3(4, 128, 1), blk>>>(
        xh, xl, wh + 2*NW, wl + 2*NW, DIM, 0, 0, 1.0f,
        nullptr, Vth, Vtl, (size_t)DIM * NSEQ, NSEQ);

    // Scores: S = (Q/sqrt(d)) @ K^T per batch (M=N=4096, K=512)
    mma_gemm<0><<<dim3(32, 32, BATCH), blk>>>(
        Qh, Ql, Kh, Kl, DIM, (size_t)NSEQ * DIM, (size_t)NSEQ * DIM, 1.0f,
        S, nullptr, nullptr, (size_t)NSEQ * NSEQ, NSEQ);

    // Softmax + hi/lo split of P
    softmax_split<<<MTOT, blk>>>(S, Ph, Pl);

    // O = P @ (V^T)^T per batch (M=4096, N=512, K=4096)
    mma_gemm<0><<<dim3(4, 32, BATCH), blk>>>(
        Ph, Pl, Vth, Vtl, NSEQ, (size_t)NSEQ * NSEQ, (size_t)DIM * NSEQ, 1.0f,
        out, nullptr, nullptr, (size_t)NSEQ * DIM, DIM);
}

// round 5
// speedup vs baseline: 7.0577x; 2.5980x over previous
#include <cuda_runtime.h>
#include <cuda_fp16.h>
#include <cstdint>
#include <math.h>

#define BATCH   4
#define NSEQ    4096
#define DIM     512
#define MTOT    (BATCH*NSEQ)   // 16384

// ---------------- scratch (allocation-free rule: device globals) ----------------
__device__ __align__(256) __half g_x16[(size_t)MTOT*DIM];
__device__ __align__(256) __half g_w16[3*DIM*DIM];
__device__ __align__(256) __half g_Q [(size_t)MTOT*DIM];
__device__ __align__(256) __half g_K [(size_t)MTOT*DIM];
__device__ __align__(256) __half g_Vt[(size_t)BATCH*DIM*NSEQ];
__device__ __align__(256) float  g_S [(size_t)BATCH*NSEQ*NSEQ];
__device__ __align__(256) __half g_P [(size_t)BATCH*NSEQ*NSEQ];

// ---------------- helpers (plain sm_80-level PTX: valid on sm_103 target) -------
__device__ __forceinline__ uint32_t smem_to_u32(const void* p) {
    uint32_t a;
    asm("{ .reg .u64 t; cvta.to.shared.u64 t, %1; cvt.u32.u64 %0, t; }" : "=r"(a) : "l"(p));
    return a;
}
__device__ __forceinline__ void cp16(uint32_t dst, const void* src) {
    asm volatile("cp.async.cg.shared.global [%0], [%1], 16;" :: "r"(dst), "l"(src));
}
#define CP_COMMIT() asm volatile("cp.async.commit_group;")
#define CP_WAIT1()  asm volatile("cp.async.wait_group 1;")

#define LDSM_X4(r0,r1,r2,r3, addr) \
    asm volatile("ldmatrix.sync.aligned.m8n8.x4.shared.b16 {%0,%1,%2,%3}, [%4];" \
        : "=r"(r0), "=r"(r1), "=r"(r2), "=r"(r3) : "r"(addr))

#define MMA16816(d, a, b0, b1) \
    asm volatile("mma.sync.aligned.m16n8k16.row.col.f32.f16.f16.f32 " \
        "{%0,%1,%2,%3}, {%4,%5,%6,%7}, {%8,%9}, {%0,%1,%2,%3};" \
        : "+f"((d)[0]), "+f"((d)[1]), "+f"((d)[2]), "+f"((d)[3]) \
        : "r"((a)[0]), "r"((a)[1]), "r"((a)[2]), "r"((a)[3]), "r"(b0), "r"(b1))

// 16B-chunk XOR swizzle for a [rows][32 half] tile (64B rows)
__device__ __forceinline__ uint32_t swz(int r, int c) {
    return (uint32_t)(r * 64 + ((c ^ ((r >> 1) & 3)) << 4));
}

// ---------------------------------------------------------------------------
// Plain fp16 GEMM on mma.sync m16n8k16:  C[M,N] = scale * (A @ B^T)
// A: row-major M x K (fp16), B: row-major N x K (fp16).
// 128x128 CTA tile, BK=32, 3-stage cp.async pipeline, 8 warps (2m x 4n, 64x32).
// EPI: 0 = fp32 out * scale; 1 = fp16 out * scale; 2 = fp16 transposed (V^T).
// ---------------------------------------------------------------------------
#define STAGES      3
#define STAGE_BYTES 16384   // A 8KB + B 8KB

template<int EPI>
__global__ __launch_bounds__(256)
void mma_gemm(const __half* __restrict__ A, const __half* __restrict__ B,
              int K, size_t sA, size_t sB, float scale,
              float* __restrict__ Cf, __half* __restrict__ Ch,
              size_t sC, int ldC)
{
    __shared__ __align__(1024) char smem[STAGES * STAGE_BYTES];
    const uint32_t sm0 = smem_to_u32(smem);
    const int tid  = threadIdx.x;
    const int wid  = tid >> 5;
    const int lane = tid & 31;
    const int wm   = wid & 1;        // 0..1  (64-row half)
    const int wn   = wid >> 1;       // 0..3  (32-col quarter)
    const int bm   = blockIdx.y * 128;
    const int bn   = blockIdx.x * 128;
    const int z    = blockIdx.z;

    const __half* Ap0 = A + (size_t)z * sA + (size_t)bm * K;
    const __half* Bp0 = B + (size_t)z * sB + (size_t)bn * K;

    const int NCH = K >> 5;     // 32-wide k chunks

    float acc[4][4][4];
    #pragma unroll
    for (int i = 0; i < 4; i++)
        #pragma unroll
        for (int j = 0; j < 4; j++)
            #pragma unroll
            for (int e = 0; e < 4; e++) acc[i][j][e] = 0.f;

    // stage load: 128 rows x 4 chunks of 16B for A and for B; 4 cp.async/thread
    auto issue = [&](int i, int s) {
        const __half* Ap = Ap0 + (i << 5);
        const __half* Bp = Bp0 + (i << 5);
        uint32_t sa = sm0 + (uint32_t)s * STAGE_BYTES;
        #pragma unroll
        for (int u = 0; u < 2; u++) {
            int id = tid + u * 256;
            int r  = id >> 2;
            int c  = id & 3;
            uint32_t sw = swz(r, c);
            cp16(sa + sw,        Ap + (size_t)r * K + c * 8);
            cp16(sa + 8192 + sw, Bp + (size_t)r * K + c * 8);
        }
        CP_COMMIT();
    };

    issue(0, 0);
    issue(1, 1);

    int cs = 0;
    for (int i = 0; i < NCH; i++) {
        CP_WAIT1();
        __syncthreads();
        if (i + 2 < NCH) issue(i + 2, (cs + 2) % STAGES);

        uint32_t sa = sm0 + (uint32_t)cs * STAGE_BYTES;
        #pragma unroll
        for (int ks = 0; ks < 2; ks++) {
            uint32_t af[4][4], bfr[2][4];
            #pragma unroll
            for (int mi = 0; mi < 4; mi++) {
                int r = wm * 64 + mi * 16 + (lane & 15);
                int c = 2 * ks + (lane >> 4);
                LDSM_X4(af[mi][0], af[mi][1], af[mi][2], af[mi][3], sa + swz(r, c));
            }
            #pragma unroll
            for (int g = 0; g < 2; g++) {
                int n = wn * 32 + g * 16 + (lane & 7) + ((lane >> 4) & 1) * 8;
                int c = 2 * ks + ((lane >> 3) & 1);
                LDSM_X4(bfr[g][0], bfr[g][1], bfr[g][2], bfr[g][3],
                        sa + 8192 + swz(n, c));
            }
            #pragma unroll
            for (int mi = 0; mi < 4; mi++)
                #pragma unroll
                for (int ni = 0; ni < 4; ni++)
                    MMA16816(acc[mi][ni], af[mi],
                             bfr[ni >> 1][(ni & 1) * 2], bfr[ni >> 1][(ni & 1) * 2 + 1]);
        }
        cs = (cs + 1) % STAGES;
    }

    // ------------------------- epilogue -------------------------
    #pragma unroll
    for (int mi = 0; mi < 4; mi++) {
        int row0 = bm + wm * 64 + mi * 16 + (lane >> 2);
        #pragma unroll
        for (int ni = 0; ni < 4; ni++) {
            int col = bn + wn * 32 + ni * 8 + (lane & 3) * 2;
            float v0 = acc[mi][ni][0] * scale, v1 = acc[mi][ni][1] * scale;
            float v2 = acc[mi][ni][2] * scale, v3 = acc[mi][ni][3] * scale;
            if (EPI == 0) {
                float* base = Cf + (size_t)z * sC;
                *(float2*)(base + (size_t)row0       * ldC + col) = make_float2(v0, v1);
                *(float2*)(base + (size_t)(row0 + 8) * ldC + col) = make_float2(v2, v3);
            } else if (EPI == 1) {
                __half2 h0; h0.x = __float2half(v0); h0.y = __float2half(v1);
                __half2 h1; h1.x = __float2half(v2); h1.y = __float2half(v3);
                *(__half2*)(Ch + (size_t)row0       * ldC + col) = h0;
                *(__half2*)(Ch + (size_t)(row0 + 8) * ldC + col) = h1;
            } else {   // EPI == 2: transposed (V^T[b][dim][seq])
                float vv[4] = {v0, v1, v2, v3};
                #pragma unroll
                for (int e = 0; e < 4; e++) {
                    int m  = row0 + (e >> 1) * 8;
                    int cc = col + (e & 1);
                    int b  = m >> 12;
                    int sq = m & (NSEQ - 1);
                    Ch[(size_t)b * sC + (size_t)cc * ldC + sq] = __float2half(vv[e]);
                }
            }
        }
    }
}

// ---------------------------------------------------------------------------
// fp32 -> fp16 convert
// ---------------------------------------------------------------------------
__global__ __launch_bounds__(256)
void cvt_fp16(const float* __restrict__ in, __half* __restrict__ o, int n)
{
    int i = blockIdx.x * 256 + threadIdx.x;
    if (i < n) o[i] = __float2half(in[i]);
}

// ---------------------------------------------------------------------------
// Row softmax (4096 wide), fp16 output. One CTA (256 thr) per row.
// ---------------------------------------------------------------------------
__global__ __launch_bounds__(256)
void softmax_rows(const float* __restrict__ S, __half* __restrict__ P)
{
    const size_t row = blockIdx.x;
    const float* p = S + row * (size_t)NSEQ;
    const int tid  = threadIdx.x;
    const int lane = tid & 31;
    const int warp = tid >> 5;

    __shared__ float red[8];

    float v[16];
    float m = -3.4e38f;
    #pragma unroll
    for (int i = 0; i < 16; i++) {
        v[i] = p[tid + i * 256];
        m = fmaxf(m, v[i]);
    }
    #pragma unroll
    for (int o = 16; o > 0; o >>= 1) m = fmaxf(m, __shfl_xor_sync(0xffffffffu, m, o));
    if (lane == 0) red[warp] = m;
    __syncthreads();
    if (tid < 8) {
        float t = red[tid];
        #pragma unroll
        for (int o = 4; o > 0; o >>= 1) t = fmaxf(t, __shfl_xor_sync(0xffu, t, o));
        if (tid == 0) red[0] = t;
    }
    __syncthreads();
    m = red[0];
    __syncthreads();

    float s = 0.f;
    #pragma unroll
    for (int i = 0; i < 16; i++) {
        v[i] = expf(v[i] - m);
        s += v[i];
    }
    #pragma unroll
    for (int o = 16; o > 0; o >>= 1) s += __shfl_xor_sync(0xffffffffu, s, o);
    if (lane == 0) red[warp] = s;
    __syncthreads();
    if (tid < 8) {
        float t = red[tid];
        #pragma unroll
        for (int o = 4; o > 0; o >>= 1) t += __shfl_xor_sync(0xffu, t, o);
        if (tid == 0) red[0] = t;
    }
    __syncthreads();
    const float inv = 1.0f / red[0];

    __half* q = P + row * (size_t)NSEQ;
    #pragma unroll
    for (int i = 0; i < 16; i += 2) {
        __half2 h;
        h.x = __float2half(v[i]     * inv);
        h.y = __float2half(v[i + 1] * inv);
        // adjacent i pairs are 256 apart -> write scalars
        q[tid + i * 256]       = h.x;
        q[tid + (i + 1) * 256] = h.y;
    }
}

// ---------------------------------------------------------------------------
extern "C" void kernel_launch(void* const* d_in, const int* in_sizes, int n_in,
                              void* d_out, int out_size)
{
    const float* x  = (const float*)d_in[0];
    const float* wq = (const float*)d_in[1];
    const float* wk = (const float*)d_in[2];
    const float* wv = (const float*)d_in[3];
    float* out = (float*)d_out;

    __half *x16, *w16, *Q, *K, *Vt, *P;
    float *S;
    cudaGetSymbolAddress((void**)&x16, g_x16);
    cudaGetSymbolAddress((void**)&w16, g_w16);
    cudaGetSymbolAddress((void**)&Q,  g_Q);
    cudaGetSymbolAddress((void**)&K,  g_K);
    cudaGetSymbolAddress((void**)&Vt, g_Vt);
    cudaGetSymbolAddress((void**)&S,  g_S);
    cudaGetSymbolAddress((void**)&P,  g_P);

    const int NX = MTOT * DIM;      // 8388608
    const int NW = DIM * DIM;       // 262144
    cvt_fp16<<<(NX + 255) / 256, 256>>>(x, x16, NX);
    cvt_fp16<<<(NW + 255) / 256, 256>>>(wq, w16 + 0*NW, NW);
    cvt_fp16<<<(NW + 255) / 256, 256>>>(wk, w16 + 1*NW, NW);
    cvt_fp16<<<(NW + 255) / 256, 256>>>(wv, w16 + 2*NW, NW);

    const float inv_sqrt_d = 0.04419417382415922f;  // 1/sqrt(512)
    const dim3 blk(256);

    // Projections (M=16384, N=512, K=512); Q pre-scaled by 1/sqrt(d)
    mma_gemm<1><<<dim3(4, 128, 1), blk>>>(
        x16, w16 + 0*NW, DIM, 0, 0, inv_sqrt_d, nullptr, Q, 0, DIM);
    mma_gemm<1><<<dim3(4, 128, 1), blk>>>(
        x16, w16 + 1*NW, DIM, 0, 0, 1.0f, nullptr, K, 0, DIM);
    mma_gemm<2><<<dim3(4, 128, 1), blk>>>(
        x16, w16 + 2*NW, DIM, 0, 0, 1.0f, nullptr, Vt, (size_t)DIM * NSEQ, NSEQ);

    // Scores: S = (Q/sqrt(d)) @ K^T per batch (M=N=4096, K=512)
    mma_gemm<0><<<dim3(32, 32, BATCH), blk>>>(
        Q, K, DIM, (size_t)NSEQ * DIM, (size_t)NSEQ * DIM, 1.0f,
        S, nullptr, (size_t)NSEQ * NSEQ, NSEQ);

    // Softmax rows -> fp16 P
    softmax_rows<<<MTOT, blk>>>(S, P);

    // O = P @ (V^T)^T per batch (M=4096, N=512, K=4096)
    mma_gemm<0><<<dim3(4, 32, BATCH), blk>>>(
        P, Vt, NSEQ, (size_t)NSEQ * NSEQ, (size_t)DIM * NSEQ, 1.0f,
        out, nullptr, (size_t)NSEQ * DIM, DIM);
}

// round 7
// speedup vs baseline: 7.8116x; 1.1068x over previous
#include <cuda_runtime.h>
#include <cuda_fp16.h>
#include <cstdint>
#include <math.h>

#define BATCH   4
#define NSEQ    4096
#define DIM     512
#define MTOT    (BATCH*NSEQ)   // 16384
#define NBT     32             // N column tiles per batch in scores GEMM

// ---------------- scratch (allocation-free rule: device globals) ----------------
__device__ __align__(256) __half g_x16[(size_t)MTOT*DIM];
__device__ __align__(256) __half g_w16[3*DIM*DIM];
__device__ __align__(256) __half g_Q [(size_t)MTOT*DIM];
__device__ __align__(256) __half g_K [(size_t)MTOT*DIM];
__device__ __align__(256) __half g_Vt[(size_t)BATCH*DIM*NSEQ];
__device__ __align__(256) __half g_P [(size_t)BATCH*NSEQ*NSEQ];   // unnormalized exp(S)
__device__ __align__(256) float  g_ps[(size_t)BATCH*NBT*NSEQ];    // per-CTA row partial sums
__device__ __align__(256) float  g_ri[(size_t)MTOT];              // 1 / row sum

// ---------------- helpers (plain sm_80-level PTX: valid on sm_103 target) -------
__device__ __forceinline__ uint32_t smem_to_u32(const void* p) {
    uint32_t a;
    asm("{ .reg .u64 t; cvta.to.shared.u64 t, %1; cvt.u32.u64 %0, t; }" : "=r"(a) : "l"(p));
    return a;
}
__device__ __forceinline__ void cp16(uint32_t dst, const void* src) {
    asm volatile("cp.async.cg.shared.global [%0], [%1], 16;" :: "r"(dst), "l"(src));
}
#define CP_COMMIT() asm volatile("cp.async.commit_group;")
#define CP_WAIT1()  asm volatile("cp.async.wait_group 1;")

#define LDSM_X4(r0,r1,r2,r3, addr) \
    asm volatile("ldmatrix.sync.aligned.m8n8.x4.shared.b16 {%0,%1,%2,%3}, [%4];" \
        : "=r"(r0), "=r"(r1), "=r"(r2), "=r"(r3) : "r"(addr))

#define MMA16816(d, a, b0, b1) \
    asm volatile("mma.sync.aligned.m16n8k16.row.col.f32.f16.f16.f32 " \
        "{%0,%1,%2,%3}, {%4,%5,%6,%7}, {%8,%9}, {%0,%1,%2,%3};" \
        : "+f"((d)[0]), "+f"((d)[1]), "+f"((d)[2]), "+f"((d)[3]) \
        : "r"((a)[0]), "r"((a)[1]), "r"((a)[2]), "r"((a)[3]), "r"(b0), "r"(b1))

// 16B-chunk XOR swizzle for a [rows][32 half] tile (64B rows)
__device__ __forceinline__ uint32_t swz(int r, int c) {
    return (uint32_t)(r * 64 + ((c ^ ((r >> 1) & 3)) << 4));
}

// ---------------------------------------------------------------------------
// fp16 GEMM on mma.sync m16n8k16:  C[M,N] = scale * (A @ B^T)
// A: row-major M x K (fp16), B: row-major N x K (fp16).
// 128x128 CTA tile, BK=32, 3-stage cp.async pipeline, 8 warps (2m x 4n, 64x32).
// EPI: 1 = fp16 out * scale
//      2 = fp16 out transposed (V^T[b][dim][seq])
//      3 = exp(acc*scale) -> fp16 P~ + per-CTA row partial sums to aux
//      4 = fp32 out * aux[row]  (row-wise normalization, scale folded in aux)
// ---------------------------------------------------------------------------
#define STAGES      3
#define STAGE_BYTES 16384   // A 8KB + B 8KB

template<int EPI>
__global__ __launch_bounds__(256)
void mma_gemm(const __half* __restrict__ A, const __half* __restrict__ B,
              int K, size_t sA, size_t sB, float scale,
              float* __restrict__ Cf, __half* __restrict__ Ch,
              size_t sC, int ldC, float* __restrict__ aux)
{
    __shared__ __align__(1024) char smem[STAGES * STAGE_BYTES];
    const uint32_t sm0 = smem_to_u32(smem);
    const int tid  = threadIdx.x;
    const int wid  = tid >> 5;
    const int lane = tid & 31;
    const int wm   = wid & 1;        // 0..1  (64-row half)
    const int wn   = wid >> 1;       // 0..3  (32-col quarter)
    const int bm   = blockIdx.y * 128;
    const int bn   = blockIdx.x * 128;
    const int z    = blockIdx.z;

    const __half* Ap0 = A + (size_t)z * sA + (size_t)bm * K;
    const __half* Bp0 = B + (size_t)z * sB + (size_t)bn * K;

    const int NCH = K >> 5;     // 32-wide k chunks

    float acc[4][4][4];
    #pragma unroll
    for (int i = 0; i < 4; i++)
        #pragma unroll
        for (int j = 0; j < 4; j++)
            #pragma unroll
            for (int e = 0; e < 4; e++) acc[i][j][e] = 0.f;

    auto issue = [&](int i, int s) {
        const __half* Ap = Ap0 + (i << 5);
        const __half* Bp = Bp0 + (i << 5);
        uint32_t sa = sm0 + (uint32_t)s * STAGE_BYTES;
        #pragma unroll
        for (int u = 0; u < 2; u++) {
            int id = tid + u * 256;
            int r  = id >> 2;
            int c  = id & 3;
            uint32_t sw = swz(r, c);
            cp16(sa + sw,        Ap + (size_t)r * K + c * 8);
            cp16(sa + 8192 + sw, Bp + (size_t)r * K + c * 8);
        }
        CP_COMMIT();
    };

    issue(0, 0);
    issue(1, 1);

    int cs = 0;
    for (int i = 0; i < NCH; i++) {
        CP_WAIT1();
        __syncthreads();
        if (i + 2 < NCH) issue(i + 2, (cs + 2) % STAGES);

        uint32_t sa = sm0 + (uint32_t)cs * STAGE_BYTES;
        #pragma unroll
        for (int ks = 0; ks < 2; ks++) {
            uint32_t af[4][4], bfr[2][4];
            #pragma unroll
            for (int mi = 0; mi < 4; mi++) {
                int r = wm * 64 + mi * 16 + (lane & 15);
                int c = 2 * ks + (lane >> 4);
                LDSM_X4(af[mi][0], af[mi][1], af[mi][2], af[mi][3], sa + swz(r, c));
            }
            #pragma unroll
            for (int g = 0; g < 2; g++) {
                int n = wn * 32 + g * 16 + (lane & 7) + ((lane >> 4) & 1) * 8;
                int c = 2 * ks + ((lane >> 3) & 1);
                LDSM_X4(bfr[g][0], bfr[g][1], bfr[g][2], bfr[g][3],
                        sa + 8192 + swz(n, c));
            }
            #pragma unroll
            for (int mi = 0; mi < 4; mi++)
                #pragma unroll
                for (int ni = 0; ni < 4; ni++)
                    MMA16816(acc[mi][ni], af[mi],
                             bfr[ni >> 1][(ni & 1) * 2], bfr[ni >> 1][(ni & 1) * 2 + 1]);
        }
        cs = (cs + 1) % STAGES;
    }

    // ------------------------- epilogues -------------------------
    if (EPI == 1) {
        #pragma unroll
        for (int mi = 0; mi < 4; mi++) {
            int row0 = bm + wm * 64 + mi * 16 + (lane >> 2);
            #pragma unroll
            for (int ni = 0; ni < 4; ni++) {
                int col = bn + wn * 32 + ni * 8 + (lane & 3) * 2;
                __half2 h0 = __floats2half2_rn(acc[mi][ni][0] * scale, acc[mi][ni][1] * scale);
                __half2 h1 = __floats2half2_rn(acc[mi][ni][2] * scale, acc[mi][ni][3] * scale);
                *(__half2*)(Ch + (size_t)row0       * ldC + col) = h0;
                *(__half2*)(Ch + (size_t)(row0 + 8) * ldC + col) = h1;
            }
        }
    } else if (EPI == 2) {       // transposed (V^T[b][dim][seq])
        #pragma unroll
        for (int mi = 0; mi < 4; mi++) {
            int row0 = bm + wm * 64 + mi * 16 + (lane >> 2);
            #pragma unroll
            for (int ni = 0; ni < 4; ni++) {
                int col = bn + wn * 32 + ni * 8 + (lane & 3) * 2;
                float vv[4] = {acc[mi][ni][0], acc[mi][ni][1],
                               acc[mi][ni][2], acc[mi][ni][3]};
                #pragma unroll
                for (int e = 0; e < 4; e++) {
                    int m  = row0 + (e >> 1) * 8;
                    int cc = col + (e & 1);
                    int b  = m >> 12;
                    int sq = m & (NSEQ - 1);
                    Ch[(size_t)b * sC + (size_t)cc * ldC + sq] = __float2half(vv[e]);
                }
            }
        }
    } else if (EPI == 3) {       // exp epilogue + row partial sums
        __shared__ float psmem[4][128];
        __half* Cz = Ch + (size_t)z * sC;
        float rs[4][2] = {};
        #pragma unroll
        for (int mi = 0; mi < 4; mi++) {
            int row0 = bm + wm * 64 + mi * 16 + (lane >> 2);
            #pragma unroll
            for (int ni = 0; ni < 4; ni++) {
                int col = bn + wn * 32 + ni * 8 + (lane & 3) * 2;
                float e0 = __expf(acc[mi][ni][0] * scale);
                float e1 = __expf(acc[mi][ni][1] * scale);
                float e2 = __expf(acc[mi][ni][2] * scale);
                float e3 = __expf(acc[mi][ni][3] * scale);
                *(__half2*)(Cz + (size_t)row0       * ldC + col) = __floats2half2_rn(e0, e1);
                *(__half2*)(Cz + (size_t)(row0 + 8) * ldC + col) = __floats2half2_rn(e2, e3);
                rs[mi][0] += e0 + e1;
                rs[mi][1] += e2 + e3;
            }
        }
        #pragma unroll
        for (int mi = 0; mi < 4; mi++)
            #pragma unroll
            for (int h = 0; h < 2; h++) {
                float t = rs[mi][h];
                t += __shfl_xor_sync(0xffffffffu, t, 1);
                t += __shfl_xor_sync(0xffffffffu, t, 2);
                if ((lane & 3) == 0)
                    psmem[wn][wm * 64 + mi * 16 + (lane >> 2) + h * 8] = t;
            }
        __syncthreads();
        if (tid < 128) {
            float t = psmem[0][tid] + psmem[1][tid] + psmem[2][tid] + psmem[3][tid];
            aux[(size_t)z * (NBT * NSEQ) + (size_t)blockIdx.x * NSEQ + bm + tid] = t;
        }
    } else {                      // EPI == 4: fp32 out, row-normalized
        float* base = Cf + (size_t)z * sC;
        const float* Rv = aux + (size_t)z * NSEQ;
        #pragma unroll
        for (int mi = 0; mi < 4; mi++) {
            int row0 = bm + wm * 64 + mi * 16 + (lane >> 2);
            float i0 = Rv[row0];
            float i1 = Rv[row0 + 8];
            #pragma unroll
            for (int ni = 0; ni < 4; ni++) {
                int col = bn + wn * 32 + ni * 8 + (lane & 3) * 2;
                *(float2*)(base + (size_t)row0       * ldC + col) =
                    make_float2(acc[mi][ni][0] * i0, acc[mi][ni][1] * i0);
                *(float2*)(base + (size_t)(row0 + 8) * ldC + col) =
                    make_float2(acc[mi][ni][2] * i1, acc[mi][ni][3] * i1);
            }
        }
    }
}

// ---------------------------------------------------------------------------
// fp32 -> fp16 convert, 4 elems/thread
// ---------------------------------------------------------------------------
__global__ __launch_bounds__(256)
void cvt_fp16(const float* __restrict__ in, __half* __restrict__ o, int n)
{
    int i = (blockIdx.x * 256 + threadIdx.x) * 4;
    if (i < n) {
        float4 v = *(const float4*)(in + i);
        *(__half2*)(o + i)     = __floats2half2_rn(v.x, v.y);
        *(__half2*)(o + i + 2) = __floats2half2_rn(v.z, v.w);
    }
}

// ---------------------------------------------------------------------------
// Reduce 32 partial sums per row -> reciprocal
// ---------------------------------------------------------------------------
__global__ __launch_bounds__(256)
void rowinv(const float* __restrict__ ps, float* __restrict__ ri)
{
    int r = blockIdx.x * 256 + threadIdx.x;   // 0..MTOT-1
    int z   = r >> 12;
    int row = r & (NSEQ - 1);
    const float* p = ps + (size_t)z * (NBT * NSEQ) + row;
    float s = 0.f;
    #pragma unroll
    for (int i = 0; i < NBT; i++) s += p[(size_t)i * NSEQ];
    ri[r] = 1.0f / s;
}

// ---------------------------------------------------------------------------
extern "C" void kernel_launch(void* const* d_in, const int* in_sizes, int n_in,
                              void* d_out, int out_size)
{
    const float* x  = (const float*)d_in[0];
    const float* wq = (const float*)d_in[1];
    const float* wk = (const float*)d_in[2];
    const float* wv = (const float*)d_in[3];
    float* out = (float*)d_out;

    __half *x16, *w16, *Q, *K, *Vt, *P;
    float *ps, *ri;
    cudaGetSymbolAddress((void**)&x16, g_x16);
    cudaGetSymbolAddress((void**)&w16, g_w16);
    cudaGetSymbolAddress((void**)&Q,  g_Q);
    cudaGetSymbolAddress((void**)&K,  g_K);
    cudaGetSymbolAddress((void**)&Vt, g_Vt);
    cudaGetSymbolAddress((void**)&P,  g_P);
    cudaGetSymbolAddress((void**)&ps, g_ps);
    cudaGetSymbolAddress((void**)&ri, g_ri);

    const int NX = MTOT * DIM;      // 8388608
    const int NW = DIM * DIM;       // 262144
    cvt_fp16<<<NX / 1024, 256>>>(x, x16, NX);
    cvt_fp16<<<NW / 1024, 256>>>(wq, w16 + 0*NW, NW);
    cvt_fp16<<<NW / 1024, 256>>>(wk, w16 + 1*NW, NW);
    cvt_fp16<<<NW / 1024, 256>>>(wv, w16 + 2*NW, NW);

    const float inv_sqrt_d = 0.04419417382415922f;  // 1/sqrt(512)
    const dim3 blk(256);

    // Projections (M=16384, N=512, K=512); Q pre-scaled by 1/sqrt(d)
    mma_gemm<1><<<dim3(4, 128, 1), blk>>>(
        x16, w16 + 0*NW, DIM, 0, 0, inv_sqrt_d, nullptr, Q, 0, DIM, nullptr);
    mma_gemm<1><<<dim3(4, 128, 1), blk>>>(
        x16, w16 + 1*NW, DIM, 0, 0, 1.0f, nullptr, K, 0, DIM, nullptr);
    mma_gemm<2><<<dim3(4, 128, 1), blk>>>(
        x16, w16 + 2*NW, DIM, 0, 0, 1.0f, nullptr, Vt, (size_t)DIM * NSEQ, NSEQ, nullptr);

    // P~ = exp(Q K^T / sqrt(d)) per batch + row partial sums  (M=N=4096, K=512)
    mma_gemm<3><<<dim3(NBT, 32, BATCH), blk>>>(
        Q, K, DIM, (size_t)NSEQ * DIM, (size_t)NSEQ * DIM, 1.0f,
        nullptr, P, (size_t)NSEQ * NSEQ, NSEQ, ps);

    // 1 / row sums
    rowinv<<<MTOT / 256, 256>>>(ps, ri);

    // O = (P~ @ (V^T)^T) * rinv per batch (M=4096, N=512, K=4096)
    mma_gemm<4><<<dim3(4, 32, BATCH), blk>>>(
        P, Vt, NSEQ, (size_t)NSEQ * NSEQ, (size_t)DIM * NSEQ, 1.0f,
        out, nullptr, (size_t)NSEQ * DIM, DIM, ri);
}

// round 8
// speedup vs baseline: 8.7110x; 1.1151x over previous
#include <cuda_runtime.h>
#include <cuda_fp16.h>
#include <cstdint>
#include <math.h>

#define BATCH   4
#define NSEQ    4096
#define DIM     512
#define MTOT    (BATCH*NSEQ)   // 16384
#define NBT     32             // N column tiles per batch in scores GEMM

// ---------------- scratch (allocation-free rule: device globals) ----------------
__device__ __align__(256) __half g_x16[(size_t)MTOT*DIM];
__device__ __align__(256) __half g_w16[3*DIM*DIM];
__device__ __align__(256) __half g_Q [(size_t)MTOT*DIM];
__device__ __align__(256) __half g_K [(size_t)MTOT*DIM];
__device__ __align__(256) __half g_Vt[(size_t)BATCH*DIM*NSEQ];
__device__ __align__(256) __half g_P [(size_t)BATCH*NSEQ*NSEQ];   // unnormalized exp(S)
__device__ __align__(256) float  g_ps[(size_t)BATCH*NBT*NSEQ];    // per-CTA row partial sums
__device__ __align__(256) float  g_ri[(size_t)MTOT];              // 1 / row sum

// ---------------- helpers (plain sm_80-level PTX: valid on sm_103 target) -------
__device__ __forceinline__ uint32_t smem_to_u32(const void* p) {
    uint32_t a;
    asm("{ .reg .u64 t; cvta.to.shared.u64 t, %1; cvt.u32.u64 %0, t; }" : "=r"(a) : "l"(p));
    return a;
}
__device__ __forceinline__ void cp16(uint32_t dst, const void* src) {
    asm volatile("cp.async.cg.shared.global [%0], [%1], 16;" :: "r"(dst), "l"(src));
}
#define CP_COMMIT() asm volatile("cp.async.commit_group;")
#define CP_WAIT1()  asm volatile("cp.async.wait_group 1;")

#define LDSM_X4(r0,r1,r2,r3, addr) \
    asm volatile("ldmatrix.sync.aligned.m8n8.x4.shared.b16 {%0,%1,%2,%3}, [%4];" \
        : "=r"(r0), "=r"(r1), "=r"(r2), "=r"(r3) : "r"(addr))

#define MMA16816(d, a, b0, b1) \
    asm volatile("mma.sync.aligned.m16n8k16.row.col.f32.f16.f16.f32 " \
        "{%0,%1,%2,%3}, {%4,%5,%6,%7}, {%8,%9}, {%0,%1,%2,%3};" \
        : "+f"((d)[0]), "+f"((d)[1]), "+f"((d)[2]), "+f"((d)[3]) \
        : "r"((a)[0]), "r"((a)[1]), "r"((a)[2]), "r"((a)[3]), "r"(b0), "r"(b1))

// 16B-chunk XOR swizzle for a [rows][32 half] tile (64B rows)
__device__ __forceinline__ uint32_t swz(int r, int c) {
    return (uint32_t)(r * 64 + ((c ^ ((r >> 1) & 3)) << 4));
}

// ---------------------------------------------------------------------------
// fp16 GEMM on mma.sync m16n8k16:  C[M,N] = scale * (A @ B^T)
// A: row-major M x K (fp16), B: row-major N x K (fp16).
// 128x128 CTA tile, BK=32, 3-stage cp.async pipeline.
// 4 warps (2m x 2n), 64x64 warp tile -> 8 LDSM_X4 feed 32 MMAs per k16.
// EPI: 1 = fp16 out * scale
//      2 = fp16 out transposed (V^T[b][dim][seq])
//      3 = exp(acc*scale) -> fp16 P~ + per-CTA row partial sums to aux
//      4 = fp32 out * aux[row]  (row-wise normalization)
// ---------------------------------------------------------------------------
#define STAGES      3
#define STAGE_BYTES 16384   // A 8KB + B 8KB

template<int EPI>
__global__ __launch_bounds__(128)
void mma_gemm(const __half* __restrict__ A, const __half* __restrict__ B,
              int K, size_t sA, size_t sB, float scale,
              float* __restrict__ Cf, __half* __restrict__ Ch,
              size_t sC, int ldC, float* __restrict__ aux)
{
    __shared__ __align__(1024) char smem[STAGES * STAGE_BYTES];   // 48KB
    const uint32_t sm0 = smem_to_u32(smem);
    const int tid  = threadIdx.x;
    const int wid  = tid >> 5;
    const int lane = tid & 31;
    const int wm   = wid & 1;        // 0..1  (64-row half)
    const int wn   = wid >> 1;       // 0..1  (64-col half)
    const int bm   = blockIdx.y * 128;
    const int bn   = blockIdx.x * 128;
    const int z    = blockIdx.z;

    const __half* Ap0 = A + (size_t)z * sA + (size_t)bm * K;
    const __half* Bp0 = B + (size_t)z * sB + (size_t)bn * K;

    const int NCH = K >> 5;     // 32-wide k chunks

    float acc[4][8][4];
    #pragma unroll
    for (int i = 0; i < 4; i++)
        #pragma unroll
        for (int j = 0; j < 8; j++)
            #pragma unroll
            for (int e = 0; e < 4; e++) acc[i][j][e] = 0.f;

    // stage load: A 128x32 + B 128x32 halves; 8 cp.async per thread
    auto issue = [&](int i, int s) {
        const __half* Ap = Ap0 + (i << 5);
        const __half* Bp = Bp0 + (i << 5);
        uint32_t sa = sm0 + (uint32_t)s * STAGE_BYTES;
        #pragma unroll
        for (int u = 0; u < 4; u++) {
            int id = tid + u * 128;
            int r  = id >> 2;
            int c  = id & 3;
            uint32_t sw = swz(r, c);
            cp16(sa + sw,        Ap + (size_t)r * K + c * 8);
            cp16(sa + 8192 + sw, Bp + (size_t)r * K + c * 8);
        }
        CP_COMMIT();
    };

    issue(0, 0);
    issue(1, 1);

    int cs = 0;
    for (int i = 0; i < NCH; i++) {
        CP_WAIT1();
        __syncthreads();
        if (i + 2 < NCH) issue(i + 2, (cs + 2) % STAGES);

        uint32_t sa = sm0 + (uint32_t)cs * STAGE_BYTES;
        #pragma unroll
        for (int ks = 0; ks < 2; ks++) {
            uint32_t af[4][4], bfr[4][4];
            #pragma unroll
            for (int mi = 0; mi < 4; mi++) {
                int r = wm * 64 + mi * 16 + (lane & 15);
                int c = 2 * ks + (lane >> 4);
                LDSM_X4(af[mi][0], af[mi][1], af[mi][2], af[mi][3], sa + swz(r, c));
            }
            #pragma unroll
            for (int g = 0; g < 4; g++) {
                int n = wn * 64 + g * 16 + (lane & 7) + ((lane >> 4) & 1) * 8;
                int c = 2 * ks + ((lane >> 3) & 1);
                LDSM_X4(bfr[g][0], bfr[g][1], bfr[g][2], bfr[g][3],
                        sa + 8192 + swz(n, c));
            }
            #pragma unroll
            for (int mi = 0; mi < 4; mi++)
                #pragma unroll
                for (int ni = 0; ni < 8; ni++)
                    MMA16816(acc[mi][ni], af[mi],
                             bfr[ni >> 1][(ni & 1) * 2], bfr[ni >> 1][(ni & 1) * 2 + 1]);
        }
        cs = (cs + 1) % STAGES;
    }

    // ------------------------- epilogues -------------------------
    if (EPI == 1) {
        #pragma unroll
        for (int mi = 0; mi < 4; mi++) {
            int row0 = bm + wm * 64 + mi * 16 + (lane >> 2);
            #pragma unroll
            for (int ni = 0; ni < 8; ni++) {
                int col = bn + wn * 64 + ni * 8 + (lane & 3) * 2;
                __half2 h0 = __floats2half2_rn(acc[mi][ni][0] * scale, acc[mi][ni][1] * scale);
                __half2 h1 = __floats2half2_rn(acc[mi][ni][2] * scale, acc[mi][ni][3] * scale);
                *(__half2*)(Ch + (size_t)row0       * ldC + col) = h0;
                *(__half2*)(Ch + (size_t)(row0 + 8) * ldC + col) = h1;
            }
        }
    } else if (EPI == 2) {       // transposed (V^T[b][dim][seq])
        #pragma unroll
        for (int mi = 0; mi < 4; mi++) {
            int row0 = bm + wm * 64 + mi * 16 + (lane >> 2);
            #pragma unroll
            for (int ni = 0; ni < 8; ni++) {
                int col = bn + wn * 64 + ni * 8 + (lane & 3) * 2;
                #pragma unroll
                for (int e = 0; e < 4; e++) {
                    int m  = row0 + (e >> 1) * 8;
                    int cc = col + (e & 1);
                    int b  = m >> 12;
                    int sq = m & (NSEQ - 1);
                    Ch[(size_t)b * sC + (size_t)cc * ldC + sq] = __float2half(acc[mi][ni][e]);
                }
            }
        }
    } else if (EPI == 3) {       // exp epilogue + row partial sums
        __half* Cz = Ch + (size_t)z * sC;
        float rs[4][2] = {};
        #pragma unroll
        for (int mi = 0; mi < 4; mi++) {
            int row0 = bm + wm * 64 + mi * 16 + (lane >> 2);
            #pragma unroll
            for (int ni = 0; ni < 8; ni++) {
                int col = bn + wn * 64 + ni * 8 + (lane & 3) * 2;
                float e0 = __expf(acc[mi][ni][0] * scale);
                float e1 = __expf(acc[mi][ni][1] * scale);
                float e2 = __expf(acc[mi][ni][2] * scale);
                float e3 = __expf(acc[mi][ni][3] * scale);
                *(__half2*)(Cz + (size_t)row0       * ldC + col) = __floats2half2_rn(e0, e1);
                *(__half2*)(Cz + (size_t)(row0 + 8) * ldC + col) = __floats2half2_rn(e2, e3);
                rs[mi][0] += e0 + e1;
                rs[mi][1] += e2 + e3;
            }
        }
        __syncthreads();                    // stage smem no longer needed -> overlay
        float* psm = (float*)smem;          // [2][128]
        #pragma unroll
        for (int mi = 0; mi < 4; mi++)
            #pragma unroll
            for (int h = 0; h < 2; h++) {
                float t = rs[mi][h];
                t += __shfl_xor_sync(0xffffffffu, t, 1);
                t += __shfl_xor_sync(0xffffffffu, t, 2);
                if ((lane & 3) == 0)
                    psm[wn * 128 + wm * 64 + mi * 16 + (lane >> 2) + h * 8] = t;
            }
        __syncthreads();
        if (tid < 128) {
            float t = psm[tid] + psm[128 + tid];
            aux[(size_t)z * (NBT * NSEQ) + (size_t)blockIdx.x * NSEQ + bm + tid] = t;
        }
    } else {                      // EPI == 4: fp32 out, row-normalized
        float* base = Cf + (size_t)z * sC;
        const float* Rv = aux + (size_t)z * NSEQ;
        #pragma unroll
        for (int mi = 0; mi < 4; mi++) {
            int row0 = bm + wm * 64 + mi * 16 + (lane >> 2);
            float i0 = Rv[row0];
            float i1 = Rv[row0 + 8];
            #pragma unroll
            for (int ni = 0; ni < 8; ni++) {
                int col = bn + wn * 64 + ni * 8 + (lane & 3) * 2;
                *(float2*)(base + (size_t)row0       * ldC + col) =
                    make_float2(acc[mi][ni][0] * i0, acc[mi][ni][1] * i0);
                *(float2*)(base + (size_t)(row0 + 8) * ldC + col) =
                    make_float2(acc[mi][ni][2] * i1, acc[mi][ni][3] * i1);
            }
        }
    }
}

// ---------------------------------------------------------------------------
// fp32 -> fp16 convert, 4 elems/thread
// ---------------------------------------------------------------------------
__global__ __launch_bounds__(256)
void cvt_fp16(const float* __restrict__ in, __half* __restrict__ o, int n)
{
    int i = (blockIdx.x * 256 + threadIdx.x) * 4;
    if (i < n) {
        float4 v = *(const float4*)(in + i);
        *(__half2*)(o + i)     = __floats2half2_rn(v.x, v.y);
        *(__half2*)(o + i + 2) = __floats2half2_rn(v.z, v.w);
    }
}

// 3 weight tensors in one launch
__global__ __launch_bounds__(256)
void cvt_fp16_w(const float* __restrict__ w0, const float* __restrict__ w1,
                const float* __restrict__ w2, __half* __restrict__ o, int nw)
{
    int i = (blockIdx.x * 256 + threadIdx.x) * 4;
    const float* src = (i < nw) ? w0 : (i < 2 * nw) ? w1 : w2;
    int j = i - ((i < nw) ? 0 : (i < 2 * nw) ? nw : 2 * nw);
    float4 v = *(const float4*)(src + j);
    *(__half2*)(o + i)     = __floats2half2_rn(v.x, v.y);
    *(__half2*)(o + i + 2) = __floats2half2_rn(v.z, v.w);
}

// ---------------------------------------------------------------------------
// Reduce 32 partial sums per row -> reciprocal
// ---------------------------------------------------------------------------
__global__ __launch_bounds__(256)
void rowinv(const float* __restrict__ ps, float* __restrict__ ri)
{
    int r = blockIdx.x * 256 + threadIdx.x;   // 0..MTOT-1
    int z   = r >> 12;
    int row = r & (NSEQ - 1);
    const float* p = ps + (size_t)z * (NBT * NSEQ) + row;
    float s = 0.f;
    #pragma unroll
    for (int i = 0; i < NBT; i++) s += p[(size_t)i * NSEQ];
    ri[r] = 1.0f / s;
}

// ---------------------------------------------------------------------------
extern "C" void kernel_launch(void* const* d_in, const int* in_sizes, int n_in,
                              void* d_out, int out_size)
{
    const float* x  = (const float*)d_in[0];
    const float* wq = (const float*)d_in[1];
    const float* wk = (const float*)d_in[2];
    const float* wv = (const float*)d_in[3];
    float* out = (float*)d_out;

    __half *x16, *w16, *Q, *K, *Vt, *P;
    float *ps, *ri;
    cudaGetSymbolAddress((void**)&x16, g_x16);
    cudaGetSymbolAddress((void**)&w16, g_w16);
    cudaGetSymbolAddress((void**)&Q,  g_Q);
    cudaGetSymbolAddress((void**)&K,  g_K);
    cudaGetSymbolAddress((void**)&Vt, g_Vt);
    cudaGetSymbolAddress((void**)&P,  g_P);
    cudaGetSymbolAddress((void**)&ps, g_ps);
    cudaGetSymbolAddress((void**)&ri, g_ri);

    const int NX = MTOT * DIM;      // 8388608
    const int NW = DIM * DIM;       // 262144
    cvt_fp16<<<NX / 1024, 256>>>(x, x16, NX);
    cvt_fp16_w<<<3 * NW / 1024, 256>>>(wq, wk, wv, w16, NW);

    const float inv_sqrt_d = 0.04419417382415922f;  // 1/sqrt(512)
    const dim3 blk(128);

    // Projections (M=16384, N=512, K=512); Q pre-scaled by 1/sqrt(d)
    mma_gemm<1><<<dim3(4, 128, 1), blk>>>(
        x16, w16 + 0*NW, DIM, 0, 0, inv_sqrt_d, nullptr, Q, 0, DIM, nullptr);
    mma_gemm<1><<<dim3(4, 128, 1), blk>>>(
        x16, w16 + 1*NW, DIM, 0, 0, 1.0f, nullptr, K, 0, DIM, nullptr);
    mma_gemm<2><<<dim3(4, 128, 1), blk>>>(
        x16, w16 + 2*NW, DIM, 0, 0, 1.0f, nullptr, Vt, (size_t)DIM * NSEQ, NSEQ, nullptr);

    // P~ = exp(Q K^T / sqrt(d)) per batch + row partial sums  (M=N=4096, K=512)
    mma_gemm<3><<<dim3(NBT, 32, BATCH), blk>>>(
        Q, K, DIM, (size_t)NSEQ * DIM, (size_t)NSEQ * DIM, 1.0f,
        nullptr, P, (size_t)NSEQ * NSEQ, NSEQ, ps);

    // 1 / row sums
    rowinv<<<MTOT / 256, 256>>>(ps, ri);

    // O = (P~ @ (V^T)^T) * rinv per batch (M=4096, N=512, K=4096)
    mma_gemm<4><<<dim3(4, 32, BATCH), blk>>>(
        P, Vt, NSEQ, (size_t)NSEQ * NSEQ, (size_t)DIM * NSEQ, 1.0f,
        out, nullptr, (size_t)NSEQ * DIM, DIM, ri);
}

// round 9
// speedup vs baseline: 9.1837x; 1.0543x over previous
#include <cuda_runtime.h>
#include <cuda_fp16.h>
#include <cstdint>
#include <math.h>

#define BATCH   4
#define NSEQ    4096
#define DIM     512
#define MTOT    (BATCH*NSEQ)   // 16384
#define NBT     32             // N column tiles per batch in scores GEMM

// ---------------- scratch (allocation-free rule: device globals) ----------------
__device__ __align__(256) __half g_x16[(size_t)MTOT*DIM];
__device__ __align__(256) __half g_w16[3*DIM*DIM];
__device__ __align__(256) __half g_Q [(size_t)MTOT*DIM];
__device__ __align__(256) __half g_K [(size_t)MTOT*DIM];
__device__ __align__(256) __half g_Vt[(size_t)BATCH*DIM*NSEQ];
__device__ __align__(256) __half g_P [(size_t)BATCH*NSEQ*NSEQ];   // unnormalized exp(S)
__device__ __align__(256) float  g_ps[(size_t)BATCH*NBT*NSEQ];    // per-CTA row partial sums
__device__ __align__(256) float  g_ri[(size_t)MTOT];              // 1 / row sum

// ---------------- helpers (plain sm_80-level PTX: valid on sm_103 target) -------
__device__ __forceinline__ uint32_t smem_to_u32(const void* p) {
    uint32_t a;
    asm("{ .reg .u64 t; cvta.to.shared.u64 t, %1; cvt.u32.u64 %0, t; }" : "=r"(a) : "l"(p));
    return a;
}
__device__ __forceinline__ void cp16(uint32_t dst, const void* src) {
    asm volatile("cp.async.cg.shared.global [%0], [%1], 16;" :: "r"(dst), "l"(src));
}
#define CP_COMMIT() asm volatile("cp.async.commit_group;")
#define CP_WAIT1()  asm volatile("cp.async.wait_group 1;")

#define LDSM_X4(r0,r1,r2,r3, addr) \
    asm volatile("ldmatrix.sync.aligned.m8n8.x4.shared.b16 {%0,%1,%2,%3}, [%4];" \
        : "=r"(r0), "=r"(r1), "=r"(r2), "=r"(r3) : "r"(addr))

#define MMA16816(d, a, b0, b1) \
    asm volatile("mma.sync.aligned.m16n8k16.row.col.f32.f16.f16.f32 " \
        "{%0,%1,%2,%3}, {%4,%5,%6,%7}, {%8,%9}, {%0,%1,%2,%3};" \
        : "+f"((d)[0]), "+f"((d)[1]), "+f"((d)[2]), "+f"((d)[3]) \
        : "r"((a)[0]), "r"((a)[1]), "r"((a)[2]), "r"((a)[3]), "r"(b0), "r"(b1))

// 16B-chunk XOR swizzle for a [rows][32 half] tile (64B rows)
__device__ __forceinline__ uint32_t swz(int r, int c) {
    return (uint32_t)(r * 64 + ((c ^ ((r >> 1) & 3)) << 4));
}

// ---------------------------------------------------------------------------
// fp16 GEMM on mma.sync m16n8k16:  C[M,N] = scale * (A @ B^T)
// A: row-major M x K (fp16), B: row-major N x K (fp16).
// 128x128 CTA tile, BK=32, 3-stage cp.async pipeline,
// 4 warps (2m x 2n), 64x64 warp tile, 2-deep register fragment pipeline:
// ldmatrix for k-step t+1 issues while MMAs for t run; the cross-chunk
// wait+sync sits between MMA batches so the HMMA pipe never drains on LDS.
// EPI: 1 = fp16 out * scale
//      2 = fp16 out transposed (V^T[b][dim][seq])
//      3 = exp(acc*scale) -> fp16 P~ + per-CTA row partial sums to aux
//      4 = fp32 out * aux[row]  (row-wise normalization)
// ---------------------------------------------------------------------------
#define STAGES      3
#define STAGE_BYTES 16384   // A 8KB + B 8KB

template<int EPI>
__global__ __launch_bounds__(128, 2)
void mma_gemm(const __half* __restrict__ A, const __half* __restrict__ B,
              int K, size_t sA, size_t sB, float scale,
              float* __restrict__ Cf, __half* __restrict__ Ch,
              size_t sC, int ldC, float* __restrict__ aux)
{
    __shared__ __align__(1024) char smem[STAGES * STAGE_BYTES];   // 48KB
    const uint32_t sm0 = smem_to_u32(smem);
    const int tid  = threadIdx.x;
    const int wid  = tid >> 5;
    const int lane = tid & 31;
    const int wm   = wid & 1;        // 0..1  (64-row half)
    const int wn   = wid >> 1;       // 0..1  (64-col half)
    const int bm   = blockIdx.y * 128;
    const int bn   = blockIdx.x * 128;
    const int z    = blockIdx.z;

    const __half* Ap0 = A + (size_t)z * sA + (size_t)bm * K;
    const __half* Bp0 = B + (size_t)z * sB + (size_t)bn * K;

    const int NCH = K >> 5;     // 32-wide k chunks

    float acc[4][8][4];
    #pragma unroll
    for (int i = 0; i < 4; i++)
        #pragma unroll
        for (int j = 0; j < 8; j++)
            #pragma unroll
            for (int e = 0; e < 4; e++) acc[i][j][e] = 0.f;

    // stage load: A 128x32 + B 128x32 halves; 8 cp.async per thread
    auto issue = [&](int i, int s) {
        const __half* Ap = Ap0 + (i << 5);
        const __half* Bp = Bp0 + (i << 5);
        uint32_t sa = sm0 + (uint32_t)s * STAGE_BYTES;
        #pragma unroll
        for (int u = 0; u < 4; u++) {
            int id = tid + u * 128;
            int r  = id >> 2;
            int c  = id & 3;
            uint32_t sw = swz(r, c);
            cp16(sa + sw,        Ap + (size_t)r * K + c * 8);
            cp16(sa + 8192 + sw, Bp + (size_t)r * K + c * 8);
        }
        CP_COMMIT();
    };

    auto ldfrag = [&](uint32_t (*fa)[4], uint32_t (*fb)[4], uint32_t sa, int ks) {
        #pragma unroll
        for (int mi = 0; mi < 4; mi++) {
            int r = wm * 64 + mi * 16 + (lane & 15);
            int c = 2 * ks + (lane >> 4);
            LDSM_X4(fa[mi][0], fa[mi][1], fa[mi][2], fa[mi][3], sa + swz(r, c));
        }
        #pragma unroll
        for (int g = 0; g < 4; g++) {
            int n = wn * 64 + g * 16 + (lane & 7) + ((lane >> 4) & 1) * 8;
            int c = 2 * ks + ((lane >> 3) & 1);
            LDSM_X4(fb[g][0], fb[g][1], fb[g][2], fb[g][3], sa + 8192 + swz(n, c));
        }
    };

    auto mma_all = [&](uint32_t (*fa)[4], uint32_t (*fb)[4]) {
        #pragma unroll
        for (int mi = 0; mi < 4; mi++)
            #pragma unroll
            for (int ni = 0; ni < 8; ni++)
                MMA16816(acc[mi][ni], fa[mi],
                         fb[ni >> 1][(ni & 1) * 2], fb[ni >> 1][(ni & 1) * 2 + 1]);
    };

    uint32_t fa[2][4][4], fb[2][4][4];

    issue(0, 0);
    issue(1, 1);
    CP_WAIT1();
    __syncthreads();
    ldfrag(fa[0], fb[0], sm0, 0);

    for (int i = 0; i < NCH; i++) {
        uint32_t sa_cur = sm0 + (uint32_t)(i % STAGES) * STAGE_BYTES;
        // k-step 2i: MMAs on buf0 while buf1 (ks=1, same stage) loads
        ldfrag(fa[1], fb[1], sa_cur, 1);
        if (i + 2 < NCH) issue(i + 2, (i + 2) % STAGES); else CP_COMMIT();
        mma_all(fa[0], fb[0]);
        // k-step 2i+1: wait for next stage, prefetch its ks=0 frags, MMA buf1
        CP_WAIT1();
        __syncthreads();
        if (i + 1 < NCH)
            ldfrag(fa[0], fb[0], sm0 + (uint32_t)((i + 1) % STAGES) * STAGE_BYTES, 0);
        mma_all(fa[1], fb[1]);
    }

    // ------------------------- epilogues -------------------------
    if (EPI == 1) {
        #pragma unroll
        for (int mi = 0; mi < 4; mi++) {
            int row0 = bm + wm * 64 + mi * 16 + (lane >> 2);
            #pragma unroll
            for (int ni = 0; ni < 8; ni++) {
                int col = bn + wn * 64 + ni * 8 + (lane & 3) * 2;
                __half2 h0 = __floats2half2_rn(acc[mi][ni][0] * scale, acc[mi][ni][1] * scale);
                __half2 h1 = __floats2half2_rn(acc[mi][ni][2] * scale, acc[mi][ni][3] * scale);
                *(__half2*)(Ch + (size_t)row0       * ldC + col) = h0;
                *(__half2*)(Ch + (size_t)(row0 + 8) * ldC + col) = h1;
            }
        }
    } else if (EPI == 2) {       // transposed (V^T[b][dim][seq])
        #pragma unroll
        for (int mi = 0; mi < 4; mi++) {
            int row0 = bm + wm * 64 + mi * 16 + (lane >> 2);
            #pragma unroll
            for (int ni = 0; ni < 8; ni++) {
                int col = bn + wn * 64 + ni * 8 + (lane & 3) * 2;
                #pragma unroll
                for (int e = 0; e < 4; e++) {
                    int m  = row0 + (e >> 1) * 8;
                    int cc = col + (e & 1);
                    int b  = m >> 12;
                    int sq = m & (NSEQ - 1);
                    Ch[(size_t)b * sC + (size_t)cc * ldC + sq] = __float2half(acc[mi][ni][e]);
                }
            }
        }
    } else if (EPI == 3) {       // exp epilogue + row partial sums
        __half* Cz = Ch + (size_t)z * sC;
        float rs[4][2] = {};
        #pragma unroll
        for (int mi = 0; mi < 4; mi++) {
            int row0 = bm + wm * 64 + mi * 16 + (lane >> 2);
            #pragma unroll
            for (int ni = 0; ni < 8; ni++) {
                int col = bn + wn * 64 + ni * 8 + (lane & 3) * 2;
                float e0 = __expf(acc[mi][ni][0] * scale);
                float e1 = __expf(acc[mi][ni][1] * scale);
                float e2 = __expf(acc[mi][ni][2] * scale);
                float e3 = __expf(acc[mi][ni][3] * scale);
                *(__half2*)(Cz + (size_t)row0       * ldC + col) = __floats2half2_rn(e0, e1);
                *(__half2*)(Cz + (size_t)(row0 + 8) * ldC + col) = __floats2half2_rn(e2, e3);
                rs[mi][0] += e0 + e1;
                rs[mi][1] += e2 + e3;
            }
        }
        __syncthreads();                    // stage smem no longer needed -> overlay
        float* psm = (float*)smem;          // [2][128]
        #pragma unroll
        for (int mi = 0; mi < 4; mi++)
            #pragma unroll
            for (int h = 0; h < 2; h++) {
                float t = rs[mi][h];
                t += __shfl_xor_sync(0xffffffffu, t, 1);
                t += __shfl_xor_sync(0xffffffffu, t, 2);
                if ((lane & 3) == 0)
                    psm[wn * 128 + wm * 64 + mi * 16 + (lane >> 2) + h * 8] = t;
            }
        __syncthreads();
        if (tid < 128) {
            float t = psm[tid] + psm[128 + tid];
            aux[(size_t)z * (NBT * NSEQ) + (size_t)blockIdx.x * NSEQ + bm + tid] = t;
        }
    } else {                      // EPI == 4: fp32 out, row-normalized
        float* base = Cf + (size_t)z * sC;
        const float* Rv = aux + (size_t)z * NSEQ;
        #pragma unroll
        for (int mi = 0; mi < 4; mi++) {
            int row0 = bm + wm * 64 + mi * 16 + (lane >> 2);
            float i0 = Rv[row0];
            float i1 = Rv[row0 + 8];
            #pragma unroll
            for (int ni = 0; ni < 8; ni++) {
                int col = bn + wn * 64 + ni * 8 + (lane & 3) * 2;
                *(float2*)(base + (size_t)row0       * ldC + col) =
                    make_float2(acc[mi][ni][0] * i0, acc[mi][ni][1] * i0);
                *(float2*)(base + (size_t)(row0 + 8) * ldC + col) =
                    make_float2(acc[mi][ni][2] * i1, acc[mi][ni][3] * i1);
            }
        }
    }
}

// ---------------------------------------------------------------------------
// fp32 -> fp16 convert, 4 elems/thread
// ---------------------------------------------------------------------------
__global__ __launch_bounds__(256)
void cvt_fp16(const float* __restrict__ in, __half* __restrict__ o, int n)
{
    int i = (blockIdx.x * 256 + threadIdx.x) * 4;
    if (i < n) {
        float4 v = *(const float4*)(in + i);
        *(__half2*)(o + i)     = __floats2half2_rn(v.x, v.y);
        *(__half2*)(o + i + 2) = __floats2half2_rn(v.z, v.w);
    }
}

// 3 weight tensors in one launch
__global__ __launch_bounds__(256)
void cvt_fp16_w(const float* __restrict__ w0, const float* __restrict__ w1,
                const float* __restrict__ w2, __half* __restrict__ o, int nw)
{
    int i = (blockIdx.x * 256 + threadIdx.x) * 4;
    const float* src = (i < nw) ? w0 : (i < 2 * nw) ? w1 : w2;
    int j = i - ((i < nw) ? 0 : (i < 2 * nw) ? nw : 2 * nw);
    float4 v = *(const float4*)(src + j);
    *(__half2*)(o + i)     = __floats2half2_rn(v.x, v.y);
    *(__half2*)(o + i + 2) = __floats2half2_rn(v.z, v.w);
}

// ---------------------------------------------------------------------------
// Reduce 32 partial sums per row -> reciprocal
// ---------------------------------------------------------------------------
__global__ __launch_bounds__(256)
void rowinv(const float* __restrict__ ps, float* __restrict__ ri)
{
    int r = blockIdx.x * 256 + threadIdx.x;   // 0..MTOT-1
    int z   = r >> 12;
    int row = r & (NSEQ - 1);
    const float* p = ps + (size_t)z * (NBT * NSEQ) + row;
    float s = 0.f;
    #pragma unroll
    for (int i = 0; i < NBT; i++) s += p[(size_t)i * NSEQ];
    ri[r] = 1.0f / s;
}

// ---------------------------------------------------------------------------
extern "C" void kernel_launch(void* const* d_in, const int* in_sizes, int n_in,
                              void* d_out, int out_size)
{
    const float* x  = (const float*)d_in[0];
    const float* wq = (const float*)d_in[1];
    const float* wk = (const float*)d_in[2];
    const float* wv = (const float*)d_in[3];
    float* out = (float*)d_out;

    __half *x16, *w16, *Q, *K, *Vt, *P;
    float *ps, *ri;
    cudaGetSymbolAddress((void**)&x16, g_x16);
    cudaGetSymbolAddress((void**)&w16, g_w16);
    cudaGetSymbolAddress((void**)&Q,  g_Q);
    cudaGetSymbolAddress((void**)&K,  g_K);
    cudaGetSymbolAddress((void**)&Vt, g_Vt);
    cudaGetSymbolAddress((void**)&P,  g_P);
    cudaGetSymbolAddress((void**)&ps, g_ps);
    cudaGetSymbolAddress((void**)&ri, g_ri);

    const int NX = MTOT * DIM;      // 8388608
    const int NW = DIM * DIM;       // 262144
    cvt_fp16<<<NX / 1024, 256>>>(x, x16, NX);
    cvt_fp16_w<<<3 * NW / 1024, 256>>>(wq, wk, wv, w16, NW);

    const float inv_sqrt_d = 0.04419417382415922f;  // 1/sqrt(512)
    const dim3 blk(128);

    // Projections (M=16384, N=512, K=512); Q pre-scaled by 1/sqrt(d)
    mma_gemm<1><<<dim3(4, 128, 1), blk>>>(
        x16, w16 + 0*NW, DIM, 0, 0, inv_sqrt_d, nullptr, Q, 0, DIM, nullptr);
    mma_gemm<1><<<dim3(4, 128, 1), blk>>>(
        x16, w16 + 1*NW, DIM, 0, 0, 1.0f, nullptr, K, 0, DIM, nullptr);
    mma_gemm<2><<<dim3(4, 128, 1), blk>>>(
        x16, w16 + 2*NW, DIM, 0, 0, 1.0f, nullptr, Vt, (size_t)DIM * NSEQ, NSEQ, nullptr);

    // P~ = exp(Q K^T / sqrt(d)) per batch + row partial sums  (M=N=4096, K=512)
    mma_gemm<3><<<dim3(NBT, 32, BATCH), blk>>>(
        Q, K, DIM, (size_t)NSEQ * DIM, (size_t)NSEQ * DIM, 1.0f,
        nullptr, P, (size_t)NSEQ * NSEQ, NSEQ, ps);

    // 1 / row sums
    rowinv<<<MTOT / 256, 256>>>(ps, ri);

    // O = (P~ @ (V^T)^T) * rinv per batch (M=4096, N=512, K=4096)
    mma_gemm<4><<<dim3(4, 32, BATCH), blk>>>(
        P, Vt, NSEQ, (size_t)NSEQ * NSEQ, (size_t)DIM * NSEQ, 1.0f,
        out, nullptr, (size_t)NSEQ * DIM, DIM, ri);
}